// round 13
// baseline (speedup 1.0000x reference)
#include <cuda_runtime.h>
#include <cuda_fp16.h>
#include <cuda_bf16.h>
#include <stdint.h>

// ============================================================================
// AWQ 4-bit linear: out[128,8192] = x[128,8192] @ dequant(W)^T + bias
// mma.sync.m16n8k16, 3-stage SMEM ring, ONE barrier per K-chunk.
// M-SPLIT: grid (128 n-tiles) x (2 m-halves) = 256 CTAs, M_TILE=64, N_TILE=64,
// 104KB smem/CTA -> 2 CTAs resident per SM. Independent CTAs overlap each
// other's barrier/scoreboard stalls (r10/r11 showed single-CTA lockstep pins
// chunk time at ~2900cyc with all pipes <50%).
// CTA: 256 threads, warp grid 4(M) x 2(N), warp tile 16x32.
// ============================================================================

#define THREADS   256
#define N_TILE    64
#define M_TILE    64
#define K_DIM     8192
#define QW_COLS   1024
#define NCHUNK    64
#define ROW_BYTES 272            // 256B data + 16B pad (conflict-free)

#define A_STAGE   (M_TILE * ROW_BYTES)   // 17408
#define B_STAGE   (N_TILE * ROW_BYTES)   // 17408
#define STAGE_SZ  (A_STAGE + B_STAGE)    // 34816
#define NSTAGE    3
#define SMEM_TOTAL (NSTAGE * STAGE_SZ)   // 104448 bytes -> 2 CTAs/SM

#define X_ELEMS      1048576
#define SCALE_ELEMS  524288

__device__ __half g_x[X_ELEMS];
__device__ __half g_scales[SCALE_ELEMS];
__device__ int    g_dtype;   // 0 = fp32 storage, 1 = fp16 storage, 2 = bf16

// ---------------------------------------------------------------------------
// dtype detection from scales (values in (0.001, 0.02))
// ---------------------------------------------------------------------------
__global__ void detect_dtype_kernel(const uint32_t* __restrict__ scales_raw) {
    const int lane = threadIdx.x;
    int cntHi = 0, cntLo = 0;
#pragma unroll
    for (int i = 0; i < 8; i++) {
        const uint32_t w = scales_raw[lane * 8 + i];
        const uint32_t eHi = (w >> 23) & 0xFF;
        const uint32_t eLo = (w >> 7) & 0xFF;
        cntHi += (eHi >= 110 && eHi <= 126);
        cntLo += (eLo >= 110 && eLo <= 126);
    }
#pragma unroll
    for (int off = 16; off > 0; off >>= 1) {
        cntHi += __shfl_xor_sync(0xFFFFFFFF, cntHi, off);
        cntLo += __shfl_xor_sync(0xFFFFFFFF, cntLo, off);
    }
    if (lane == 0) {
        int dt;
        if (cntHi > 192) dt = (cntLo > 192) ? 2 : 0;
        else             dt = 1;
        g_dtype = dt;
    }
}

__global__ void convert_kernel(const void* __restrict__ src, __half* __restrict__ dst, int n) {
    const int dt = g_dtype;
    const int stride = gridDim.x * blockDim.x;
    int i = blockIdx.x * blockDim.x + threadIdx.x;
    if (dt == 0) {
        const float4* s4 = (const float4*)src;
        for (; i < n / 4; i += stride) {
            const float4 v = s4[i];
            __half2 lo = __floats2half2_rn(v.x, v.y);
            __half2 hi = __floats2half2_rn(v.z, v.w);
            uint2 o;
            o.x = *reinterpret_cast<uint32_t*>(&lo);
            o.y = *reinterpret_cast<uint32_t*>(&hi);
            *reinterpret_cast<uint2*>(dst + i * 4) = o;
        }
    } else if (dt == 2) {
        const __nv_bfloat162* s2 = (const __nv_bfloat162*)src;
        for (; i < n / 4; i += stride) {
            const __nv_bfloat162 a = s2[i * 2], b = s2[i * 2 + 1];
            __half2 lo = __floats2half2_rn(__bfloat162float(a.x), __bfloat162float(a.y));
            __half2 hi = __floats2half2_rn(__bfloat162float(b.x), __bfloat162float(b.y));
            uint2 o;
            o.x = *reinterpret_cast<uint32_t*>(&lo);
            o.y = *reinterpret_cast<uint32_t*>(&hi);
            *reinterpret_cast<uint2*>(dst + i * 4) = o;
        }
    } else {
        const uint2* s2 = (const uint2*)src;
        for (; i < n / 4; i += stride)
            *reinterpret_cast<uint2*>(dst + i * 4) = s2[i];
    }
}

// ---------------------------------------------------------------------------
// GEMM helpers
// ---------------------------------------------------------------------------
static __device__ __forceinline__ uint32_t smem_u32(const void* p) {
    uint32_t r;
    asm("{ .reg .u64 t; cvta.to.shared.u64 t, %1; cvt.u32.u64 %0, t; }" : "=r"(r) : "l"(p));
    return r;
}
static __device__ __forceinline__ uint32_t h2u(__half2 h) {
    return *reinterpret_cast<uint32_t*>(&h);
}
static __device__ __forceinline__ void cp_async16(uint32_t dst, const void* src) {
    asm volatile("cp.async.cg.shared.global [%0], [%1], 16;" :: "r"(dst), "l"(src) : "memory");
}
static __device__ __forceinline__ void cp_commit() {
    asm volatile("cp.async.commit_group;" ::: "memory");
}
template <int N>
static __device__ __forceinline__ void cp_wait() {
    asm volatile("cp.async.wait_group %0;" :: "n"(N) : "memory");
}
static __device__ __forceinline__ void ldsm_x4(uint32_t* r, uint32_t addr) {
    asm volatile("ldmatrix.sync.aligned.m8n8.x4.shared.b16 {%0,%1,%2,%3}, [%4];"
                 : "=r"(r[0]), "=r"(r[1]), "=r"(r[2]), "=r"(r[3]) : "r"(addr));
}
static __device__ __forceinline__ void mma16816(float* d, const uint32_t* a, const uint32_t* b) {
    asm volatile("mma.sync.aligned.m16n8k16.row.col.f32.f16.f16.f32 "
                 "{%0,%1,%2,%3}, {%4,%5,%6,%7}, {%8,%9}, {%0,%1,%2,%3};"
                 : "+f"(d[0]), "+f"(d[1]), "+f"(d[2]), "+f"(d[3])
                 : "r"(a[0]), "r"(a[1]), "r"(a[2]), "r"(a[3]), "r"(b[0]), "r"(b[1]));
}

// Dequant one packed int32 (8 nibbles n0..n7) -> 8 fp16 in LOGICAL order.
static __device__ __forceinline__ void dq_sts(uint32_t q, __half2 zp, __half2 s, uint32_t addr) {
    uint32_t h0, h1, h2, h3;
    asm("lop3.b32 %0, %1, 0x000F000F, 0x64006400, 0xEA;" : "=r"(h0) : "r"(q));        // (n0,n4)
    asm("lop3.b32 %0, %1, 0x000F000F, 0x64006400, 0xEA;" : "=r"(h1) : "r"(q >> 4));   // (n1,n5)
    asm("lop3.b32 %0, %1, 0x000F000F, 0x64006400, 0xEA;" : "=r"(h2) : "r"(q >> 8));   // (n2,n6)
    asm("lop3.b32 %0, %1, 0x000F000F, 0x64006400, 0xEA;" : "=r"(h3) : "r"(q >> 12));  // (n3,n7)
    uint32_t w0 = h2u(__hmul2(__hsub2(*reinterpret_cast<__half2*>(&h0), zp), s));
    uint32_t w1 = h2u(__hmul2(__hsub2(*reinterpret_cast<__half2*>(&h1), zp), s));
    uint32_t w2 = h2u(__hmul2(__hsub2(*reinterpret_cast<__half2*>(&h2), zp), s));
    uint32_t w3 = h2u(__hmul2(__hsub2(*reinterpret_cast<__half2*>(&h3), zp), s));
    uint32_t l0 = __byte_perm(w0, w1, 0x5410);  // (n0,n1)
    uint32_t l1 = __byte_perm(w2, w3, 0x5410);  // (n2,n3)
    uint32_t l2 = __byte_perm(w0, w1, 0x7632);  // (n4,n5)
    uint32_t l3 = __byte_perm(w2, w3, 0x7632);  // (n6,n7)
    asm volatile("st.shared.v4.b32 [%0], {%1,%2,%3,%4};"
                 :: "r"(addr), "r"(l0), "r"(l1), "r"(l2), "r"(l3) : "memory");
}

struct BRegs {
    uint4 w;            // 4 consecutive packed words (32 nibbles) of one n-row
    __half s;
    int zw;
};

extern __shared__ char dyn_smem[];

__global__ void __launch_bounds__(THREADS, 2)
awq_kernel(const int* __restrict__ qweight, const int* __restrict__ qzeros,
           const float* __restrict__ bias, float* __restrict__ out)
{
    const __half* x = g_x;
    const __half* scales = g_scales;
    const uint32_t sb = smem_u32(dyn_smem);
    const int tid = threadIdx.x;
    const int wid = tid >> 5;
    const int lid = tid & 31;
    const int n0 = blockIdx.x * N_TILE;
    const int m0 = blockIdx.y * M_TILE;

    // ---- A fill mapping: 1024 16B-slots (64 rows x 16 units), 4 per thread ----
    uint32_t a_dst_off[4], a_src_off[4];
#pragma unroll
    for (int it = 0; it < 4; it++) {
        const int j = tid + THREADS * it;
        const int row = j >> 4, u = j & 15;       // row 0..63, unit 0..15
        a_dst_off[it] = (uint32_t)(row * ROW_BYTES + u * 16);
        a_src_off[it] = (uint32_t)((m0 + row) * K_DIM + u * 8);
    }
    // ---- B dequant mapping: thread -> row bg (0..63), word-quad bq (0..3) ----
    const int bg = tid >> 2, bq = tid & 3;
    uint32_t b_off[4];
#pragma unroll
    for (int j = 0; j < 4; j++)
        b_off[j] = (uint32_t)(bg * ROW_BYTES + (bq * 4 + j) * 16);
    const int* qb0 = qweight + (size_t)(n0 + bg) * QW_COLS + bq * 4;
    const __half* sRow = scales + (n0 + bg) * 64;
    const int* zRow = qzeros + (n0 + bg) * 8;

    // ---- compute-side addressing: warp grid 4(M) x 2(N), warp tile 16x32 ----
    const int warp_m = wid >> 1;                  // 0..3 -> rows [warp_m*16, +16)
    const int warp_n = wid & 1;                   // 0..1 -> cols [warp_n*32, +32)
    const uint32_t rowA_off =
        (uint32_t)((warp_m * 16 + (lid & 15)) * ROW_BYTES + ((lid >> 4) & 1) * 16);
    const int gB = lid >> 3, rB = lid & 7;
    uint32_t bB_off[2];
#pragma unroll
    for (int pair = 0; pair < 2; pair++)
        bB_off[pair] = (uint32_t)((warp_n * 32 + pair * 16 + (gB >> 1) * 8 + rB) * ROW_BYTES
                                  + (gB & 1) * 16);

    float acc[4][4];
#pragma unroll
    for (int nt = 0; nt < 4; nt++)
#pragma unroll
        for (int e = 0; e < 4; e++) acc[nt][e] = 0.0f;

    auto fill_A = [&](int i, int stage) {
        const uint32_t as = sb + stage * STAGE_SZ;
        const __half* xp = x + i * 128;
#pragma unroll
        for (int it = 0; it < 4; it++)
            cp_async16(as + a_dst_off[it], xp + a_src_off[it]);
        cp_commit();
    };
    auto load_B = [&](int i, BRegs& r) {
        r.w = *reinterpret_cast<const uint4*>(qb0 + i * 16);
        r.s = sRow[i];
        r.zw = zRow[i >> 3];
    };
    auto store_B = [&](int i, int stage, const BRegs& r) {
        const uint32_t bb = sb + stage * STAGE_SZ + A_STAGE;
        const int z = (r.zw >> ((i & 7) * 4)) & 15;
        const __half2 zp = __float2half2_rn(1024.0f + (float)z);
        const __half2 s2 = __half2half2(r.s);
        dq_sts(r.w.x, zp, s2, bb + b_off[0]);
        dq_sts(r.w.y, zp, s2, bb + b_off[1]);
        dq_sts(r.w.z, zp, s2, bb + b_off[2]);
        dq_sts(r.w.w, zp, s2, bb + b_off[3]);
    };
    auto compute = [&](int stage) {
        const uint32_t ab = sb + stage * STAGE_SZ;
        const uint32_t bb = ab + A_STAGE;
#pragma unroll
        for (int w = 0; w < 8; w++) {
            uint32_t af[4], bf[2][4];
            ldsm_x4(af, ab + rowA_off + 32 * w);
            ldsm_x4(bf[0], bb + bB_off[0] + 32 * w);
            ldsm_x4(bf[1], bb + bB_off[1] + 32 * w);
            mma16816(acc[0], af, bf[0] + 0);
            mma16816(acc[1], af, bf[0] + 2);
            mma16816(acc[2], af, bf[1] + 0);
            mma16816(acc[3], af, bf[1] + 2);
        }
    };

    // ---- prologue: chunks 0,1 into stages 0,1; regs for chunk 2 ----
    fill_A(0, 0);
    fill_A(1, 1);
    BRegs rcur, rnext;
    load_B(0, rcur);
    load_B(1, rnext);
    store_B(0, 0, rcur);
    store_B(1, 1, rnext);
    load_B(2, rcur);                 // rcur holds chunk 2 data for iter 0

    // ---- mainloop: ONE barrier per chunk; compute first, then refill ----
#pragma unroll 1
    for (int i = 0; i < NCHUNK; i++) {
        if (i + 2 < NCHUNK) cp_wait<1>(); else cp_wait<0>();
        __syncthreads();             // A(i)+B(i) visible; stage (i+2)%3 free
        compute(i % 3);
        if (i + 2 < NCHUNK) {
            store_B(i + 2, (i + 2) % 3, rcur);
            fill_A(i + 2, (i + 2) % 3);
        }
        if (i + 3 < NCHUNK) load_B(i + 3, rnext);
        rcur = rnext;
    }

    // ---- epilogue: fp16 round (match fp16 einsum), + fp32 bias ----
    const int r0 = lid >> 2;
    const int c0 = (lid & 3) * 2;
#pragma unroll
    for (int nt = 0; nt < 4; nt++) {
        const int n = n0 + warp_n * 32 + nt * 8 + c0;
        const float bx = bias[n], by = bias[n + 1];
        const int m = m0 + warp_m * 16 + r0;
        float2 o0, o1;
        o0.x = __half2float(__float2half_rn(acc[nt][0])) + bx;
        o0.y = __half2float(__float2half_rn(acc[nt][1])) + by;
        o1.x = __half2float(__float2half_rn(acc[nt][2])) + bx;
        o1.y = __half2float(__float2half_rn(acc[nt][3])) + by;
        *reinterpret_cast<float2*>(out + (size_t)m * 8192 + n) = o0;
        *reinterpret_cast<float2*>(out + (size_t)(m + 8) * 8192 + n) = o1;
    }
}

// ===========================================================================
// Host: bind inputs BY ELEMENT COUNT (all distinct) — immune to ordering.
//   x 1048576 | qweight 8388608 | scales 524288 | qzeros 65536 | bias 8192
// ===========================================================================
extern "C" void kernel_launch(void* const* d_in, const int* in_sizes, int n_in,
                              void* d_out, int out_size) {
    const void* x_raw = nullptr;
    const int* qweight = nullptr;
    const void* scales_raw = nullptr;
    const int* qzeros = nullptr;
    const float* bias = nullptr;

    for (int i = 0; i < n_in; i++) {
        switch (in_sizes[i]) {
            case X_ELEMS:     x_raw      = d_in[i];               break;
            case 8388608:     qweight    = (const int*)d_in[i];   break;
            case SCALE_ELEMS: scales_raw = d_in[i];               break;
            case 65536:       qzeros     = (const int*)d_in[i];   break;
            case 8192:        bias       = (const float*)d_in[i]; break;
            default: break;
        }
    }

    float* out = (float*)d_out;

    __half* gx = nullptr;
    __half* gs = nullptr;
    cudaGetSymbolAddress((void**)&gx, g_x);
    cudaGetSymbolAddress((void**)&gs, g_scales);

    detect_dtype_kernel<<<1, 32>>>((const uint32_t*)scales_raw);
    convert_kernel<<<256, 256>>>(x_raw, gx, X_ELEMS);
    convert_kernel<<<64, 256>>>(scales_raw, gs, SCALE_ELEMS);

    cudaFuncSetAttribute(awq_kernel, cudaFuncAttributeMaxDynamicSharedMemorySize, SMEM_TOTAL);
    dim3 grid(8192 / N_TILE, 128 / M_TILE);
    awq_kernel<<<grid, THREADS, SMEM_TOTAL>>>(qweight, qzeros, bias, out);
}